// round 9
// baseline (speedup 1.0000x reference)
#include <cuda_runtime.h>
#include <cuda_bf16.h>
#include <cstdint>

// Upsample2d (up=2, binomial 4-tap) == separable interp:
//   out[2m]   = 0.25*x[m-1] + 0.75*x[m]
//   out[2m+1] = 0.75*x[m]   + 0.25*x[m+1]
// R9: stores go through SMEM + cp.async.bulk (TMA-store path) instead of STG.
// Warp owns output rows [2r0, 2r0+8) = one contiguous 8KB gmem block; it
// computes them into its 8KB smem slab (STS.128, no L1TEX global wavefronts)
// and drains with a single bulk async copy. Loads: input rows r0-1..r0+4
// (L2-resident), intra-warp shfl halo.

#define W_IN  128
#define H_IN  128
#define W_OUT 256
#define H_OUT 256
#define WARPS 8
#define RPW   4                      // input rows per warp -> 8 output rows
#define SLAB  (8 * W_OUT)            // floats per warp slab (8KB)
// block covers WARPS*RPW = 32 input rows -> 4 blocks per image
#define SMEM_BYTES (WARPS * SLAB * 4)   // 64KB

__device__ __forceinline__ void compute_h(float4 a, int lane, float* __restrict__ h) {
    float left  = __shfl_up_sync(0xffffffffu, a.w, 1);
    float right = __shfl_down_sync(0xffffffffu, a.x, 1);
    if (lane == 0)  left  = 0.0f;
    if (lane == 31) right = 0.0f;
    h[0] = 0.25f * left + 0.75f * a.x;
    h[1] = 0.75f * a.x  + 0.25f * a.y;
    h[2] = 0.25f * a.x  + 0.75f * a.y;
    h[3] = 0.75f * a.y  + 0.25f * a.z;
    h[4] = 0.25f * a.y  + 0.75f * a.z;
    h[5] = 0.75f * a.z  + 0.25f * a.w;
    h[6] = 0.25f * a.z  + 0.75f * a.w;
    h[7] = 0.75f * a.w  + 0.25f * right;
}

__device__ __forceinline__ void sts_row(float* p,
                                        const float* __restrict__ w0,
                                        const float* __restrict__ w1,
                                        float c0, float c1) {
    float4 lo = make_float4(c0 * w0[0] + c1 * w1[0], c0 * w0[1] + c1 * w1[1],
                            c0 * w0[2] + c1 * w1[2], c0 * w0[3] + c1 * w1[3]);
    float4 hi = make_float4(c0 * w0[4] + c1 * w1[4], c0 * w0[5] + c1 * w1[5],
                            c0 * w0[6] + c1 * w1[6], c0 * w0[7] + c1 * w1[7]);
    reinterpret_cast<float4*>(p)[0] = lo;
    reinterpret_cast<float4*>(p)[1] = hi;
}

__global__ __launch_bounds__(WARPS * 32)
void Upsample_63797444215162_kernel(const float* __restrict__ x,
                                    float* __restrict__ out) {
    extern __shared__ float smem[];

    const int tid  = threadIdx.x;
    const int warp = tid >> 5;
    const int lane = tid & 31;
    const int img  = blockIdx.x >> 2;           // 4 blocks per image
    const int quad = blockIdx.x & 3;

    const float* __restrict__ xi = x   + (size_t)img * (H_IN * W_IN);
    float*       __restrict__ oi = out + (size_t)img * (H_OUT * W_OUT);

    const int r0 = quad * (WARPS * RPW) + warp * RPW;   // input strip start
    const int c0 = lane * 4;                            // input col base
    float* wbuf = smem + warp * SLAB;                   // 8KB slab
    float* wout = wbuf + lane * 8;                      // lane's 8-col window

    // Load 6 input rows: r0-1 .. r0+4 (zeros outside the image)
    float4 v[RPW + 2];
    v[0] = (r0 == 0) ? make_float4(0.f, 0.f, 0.f, 0.f)
                     : *reinterpret_cast<const float4*>(xi + (r0 - 1) * W_IN + c0);
    #pragma unroll
    for (int k = 0; k < RPW; ++k)
        v[k + 1] = *reinterpret_cast<const float4*>(xi + (r0 + k) * W_IN + c0);
    v[RPW + 1] = (r0 + RPW == H_IN)
                     ? make_float4(0.f, 0.f, 0.f, 0.f)
                     : *reinterpret_cast<const float4*>(xi + (r0 + RPW) * W_IN + c0);

    // Pairs (h(r0-1+m), h(r0+m)), m=0..4, emit local output rows 0..7:
    //   local row 2m-1 = 0.75*hp + 0.25*hc   (m >= 1)
    //   local row 2m   = 0.25*hp + 0.75*hc   (m <= 3)
    float hp[8], hc[8];
    compute_h(v[0], lane, hp);
    #pragma unroll
    for (int m = 0; m <= RPW; ++m) {
        compute_h(v[m + 1], lane, hc);
        if (m >= 1)
            sts_row(wout + (2 * m - 1) * W_OUT, hp, hc, 0.75f, 0.25f);
        if (m <= RPW - 1)
            sts_row(wout + (2 * m) * W_OUT, hp, hc, 0.25f, 0.75f);
        #pragma unroll
        for (int j = 0; j < 8; ++j) hp[j] = hc[j];
    }

    // Drain slab -> gmem with one bulk async copy (async-proxy store path)
    asm volatile("fence.proxy.async.shared::cta;" ::: "memory");
    __syncwarp();
    if (lane == 0) {
        uint32_t saddr = (uint32_t)__cvta_generic_to_shared(wbuf);
        float* gptr = oi + (size_t)(2 * r0) * W_OUT;
        asm volatile("cp.async.bulk.global.shared::cta.bulk_group [%0], [%1], %2;"
                     :: "l"(gptr), "r"(saddr), "r"((int)(SLAB * 4))
                     : "memory");
        asm volatile("cp.async.bulk.commit_group;" ::: "memory");
        asm volatile("cp.async.bulk.wait_group.read 0;" ::: "memory");
    }
}

extern "C" void kernel_launch(void* const* d_in, const int* in_sizes, int n_in,
                              void* d_out, int out_size) {
    const float* x = (const float*)d_in[0];   // [8,128,128,128] fp32
    // d_in[1] is the fixed 4x4 binomial kernel; weights folded into code.
    float* out = (float*)d_out;               // [8,128,256,256] fp32

    cudaFuncSetAttribute(Upsample_63797444215162_kernel,
                         cudaFuncAttributeMaxDynamicSharedMemorySize, SMEM_BYTES);

    const int n_img = in_sizes[0] / (H_IN * W_IN);   // B*C = 1024
    Upsample_63797444215162_kernel<<<n_img * 4, WARPS * 32, SMEM_BYTES>>>(x, out);
}

// round 10
// speedup vs baseline: 1.0376x; 1.0376x over previous
#include <cuda_runtime.h>
#include <cuda_bf16.h>

// Upsample2d (up=2, binomial 4-tap) == separable interp:
//   out[2m]   = 0.25*x[m-1] + 0.75*x[m]
//   out[2m+1] = 0.75*x[m]   + 0.25*x[m+1]
// R10: R8 (best) with the prologue halo row merged into the batched load wave
// (5 back-to-back LDG.128s, no exposed dependent latency in the prologue).
// Warp = full input row, intra-warp shfl halo, 256-bit .cs stores, grid 4096.

#define W_IN  128
#define H_IN  128
#define W_OUT 256
#define H_OUT 256
#define WARPS 8
#define RPW   4      // input rows per warp strip
// block covers WARPS*RPW = 32 input rows -> 4 blocks per image

__device__ __forceinline__ void compute_h(float4 a, int lane, float* __restrict__ h) {
    float left  = __shfl_up_sync(0xffffffffu, a.w, 1);
    float right = __shfl_down_sync(0xffffffffu, a.x, 1);
    if (lane == 0)  left  = 0.0f;
    if (lane == 31) right = 0.0f;
    h[0] = 0.25f * left + 0.75f * a.x;
    h[1] = 0.75f * a.x  + 0.25f * a.y;
    h[2] = 0.25f * a.x  + 0.75f * a.y;
    h[3] = 0.75f * a.y  + 0.25f * a.z;
    h[4] = 0.25f * a.y  + 0.75f * a.z;
    h[5] = 0.75f * a.z  + 0.25f * a.w;
    h[6] = 0.25f * a.z  + 0.75f * a.w;
    h[7] = 0.75f * a.w  + 0.25f * right;
}

__device__ __forceinline__ void store_row_v8(float* p,
                                             const float* __restrict__ w0,
                                             const float* __restrict__ w1,
                                             float c0, float c1) {
    float o0 = c0 * w0[0] + c1 * w1[0];
    float o1 = c0 * w0[1] + c1 * w1[1];
    float o2 = c0 * w0[2] + c1 * w1[2];
    float o3 = c0 * w0[3] + c1 * w1[3];
    float o4 = c0 * w0[4] + c1 * w1[4];
    float o5 = c0 * w0[5] + c1 * w1[5];
    float o6 = c0 * w0[6] + c1 * w1[6];
    float o7 = c0 * w0[7] + c1 * w1[7];
    asm volatile("st.global.cs.v8.f32 [%0], {%1,%2,%3,%4,%5,%6,%7,%8};"
                 :: "l"(p), "f"(o0), "f"(o1), "f"(o2), "f"(o3),
                    "f"(o4), "f"(o5), "f"(o6), "f"(o7)
                 : "memory");
}

__global__ __launch_bounds__(WARPS * 32)
void Upsample_63797444215162_kernel(const float* __restrict__ x,
                                    float* __restrict__ out) {
    const int tid  = threadIdx.x;
    const int warp = tid >> 5;
    const int lane = tid & 31;
    const int img  = blockIdx.x >> 2;           // 4 blocks per image
    const int quad = blockIdx.x & 3;

    const float* __restrict__ xi = x   + (size_t)img * (H_IN * W_IN);
    float*       __restrict__ oi = out + (size_t)img * (H_OUT * W_OUT);

    const int r0 = quad * (WARPS * RPW) + warp * RPW;   // strip start row
    const int c0 = lane * 4;                            // input col base
    const int oc = lane * 8;                            // output col base

    // Batched loads: halo row (r0-1, clamped) + RPW body rows, all issued
    // back-to-back. For r0==0 the clamped load reads row 0; its value is
    // discarded (hp forced to zero below), so correctness is unaffected.
    const int rh = (r0 == 0) ? 0 : (r0 - 1);
    float4 vh;
    float4 v[RPW];
    {
        const float* p = xi + rh * W_IN + c0;
        vh = *reinterpret_cast<const float4*>(p);
        #pragma unroll
        for (int k = 0; k < RPW; ++k)
            v[k] = *reinterpret_cast<const float4*>(xi + (r0 + k) * W_IN + c0);
    }

    float hp[8];                                        // h(n-1), rolled
    if (r0 == 0) {
        #pragma unroll
        for (int j = 0; j < 8; ++j) hp[j] = 0.0f;
    } else {
        compute_h(vh, lane, hp);
    }

    #pragma unroll
    for (int k = 0; k < RPW; ++k) {
        const int n = r0 + k;
        float h[8];
        compute_h(v[k], lane, h);

        // out row 2n-1 = 0.75*h(n-1) + 0.25*h(n)   (row -1 doesn't exist)
        if (n > 0)
            store_row_v8(oi + (2 * n - 1) * W_OUT + oc, hp, h, 0.75f, 0.25f);
        // out row 2n   = 0.25*h(n-1) + 0.75*h(n)
        store_row_v8(oi + (2 * n) * W_OUT + oc, hp, h, 0.25f, 0.75f);

        #pragma unroll
        for (int j = 0; j < 8; ++j) hp[j] = h[j];
    }

    // last output row 2H-1 = 0.75*h(H-1), owned by the last strip
    if (r0 + RPW == H_IN) {
        float z[8] = {0, 0, 0, 0, 0, 0, 0, 0};
        store_row_v8(oi + (H_OUT - 1) * W_OUT + oc, hp, z, 0.75f, 0.0f);
    }
}

extern "C" void kernel_launch(void* const* d_in, const int* in_sizes, int n_in,
                              void* d_out, int out_size) {
    const float* x = (const float*)d_in[0];   // [8,128,128,128] fp32
    // d_in[1] is the fixed 4x4 binomial kernel; weights folded into code.
    float* out = (float*)d_out;               // [8,128,256,256] fp32

    const int n_img = in_sizes[0] / (H_IN * W_IN);   // B*C = 1024
    Upsample_63797444215162_kernel<<<n_img * 4, WARPS * 32>>>(x, out);
}

// round 11
// speedup vs baseline: 1.0430x; 1.0052x over previous
#include <cuda_runtime.h>
#include <cuda_bf16.h>

// Upsample2d (up=2, binomial 4-tap) == separable interp:
//   out[2m]   = 0.25*x[m-1] + 0.75*x[m]
//   out[2m+1] = 0.75*x[m]   + 0.25*x[m+1]
// R11: R10 with RPW=8 — one front-batched wave of 9 LDG.128 (halo + 8 body
// rows, MLP_p1=9), then 17 STG.256 stores. Halves per-task prologue-latency
// exposures and halo overhead vs R10. Warp = full input row, intra-warp shfl
// halo, 256-bit .cs stores, grid 2048.

#define W_IN  128
#define H_IN  128
#define W_OUT 256
#define H_OUT 256
#define WARPS 8
#define RPW   8      // input rows per warp strip
// block covers WARPS*RPW = 64 input rows -> 2 blocks per image

__device__ __forceinline__ void compute_h(float4 a, int lane, float* __restrict__ h) {
    float left  = __shfl_up_sync(0xffffffffu, a.w, 1);
    float right = __shfl_down_sync(0xffffffffu, a.x, 1);
    if (lane == 0)  left  = 0.0f;
    if (lane == 31) right = 0.0f;
    h[0] = 0.25f * left + 0.75f * a.x;
    h[1] = 0.75f * a.x  + 0.25f * a.y;
    h[2] = 0.25f * a.x  + 0.75f * a.y;
    h[3] = 0.75f * a.y  + 0.25f * a.z;
    h[4] = 0.25f * a.y  + 0.75f * a.z;
    h[5] = 0.75f * a.z  + 0.25f * a.w;
    h[6] = 0.25f * a.z  + 0.75f * a.w;
    h[7] = 0.75f * a.w  + 0.25f * right;
}

__device__ __forceinline__ void store_row_v8(float* p,
                                             const float* __restrict__ w0,
                                             const float* __restrict__ w1,
                                             float c0, float c1) {
    float o0 = c0 * w0[0] + c1 * w1[0];
    float o1 = c0 * w0[1] + c1 * w1[1];
    float o2 = c0 * w0[2] + c1 * w1[2];
    float o3 = c0 * w0[3] + c1 * w1[3];
    float o4 = c0 * w0[4] + c1 * w1[4];
    float o5 = c0 * w0[5] + c1 * w1[5];
    float o6 = c0 * w0[6] + c1 * w1[6];
    float o7 = c0 * w0[7] + c1 * w1[7];
    asm volatile("st.global.cs.v8.f32 [%0], {%1,%2,%3,%4,%5,%6,%7,%8};"
                 :: "l"(p), "f"(o0), "f"(o1), "f"(o2), "f"(o3),
                    "f"(o4), "f"(o5), "f"(o6), "f"(o7)
                 : "memory");
}

__global__ __launch_bounds__(WARPS * 32)
void Upsample_63797444215162_kernel(const float* __restrict__ x,
                                    float* __restrict__ out) {
    const int tid  = threadIdx.x;
    const int warp = tid >> 5;
    const int lane = tid & 31;
    const int img  = blockIdx.x >> 1;           // 2 blocks per image
    const int half = blockIdx.x & 1;

    const float* __restrict__ xi = x   + (size_t)img * (H_IN * W_IN);
    float*       __restrict__ oi = out + (size_t)img * (H_OUT * W_OUT);

    const int r0 = half * (WARPS * RPW) + warp * RPW;   // strip start row
    const int c0 = lane * 4;                            // input col base
    const int oc = lane * 8;                            // output col base

    // Front-batched loads: halo row (r0-1, clamped) + RPW body rows, all
    // issued back-to-back. For r0==0 the clamped load's value is discarded
    // (hp forced to zero below).
    const int rh = (r0 == 0) ? 0 : (r0 - 1);
    float4 vh;
    float4 v[RPW];
    {
        vh = *reinterpret_cast<const float4*>(xi + rh * W_IN + c0);
        #pragma unroll
        for (int k = 0; k < RPW; ++k)
            v[k] = *reinterpret_cast<const float4*>(xi + (r0 + k) * W_IN + c0);
    }

    float hp[8];                                        // h(n-1), rolled
    if (r0 == 0) {
        #pragma unroll
        for (int j = 0; j < 8; ++j) hp[j] = 0.0f;
    } else {
        compute_h(vh, lane, hp);
    }

    #pragma unroll
    for (int k = 0; k < RPW; ++k) {
        const int n = r0 + k;
        float h[8];
        compute_h(v[k], lane, h);

        // out row 2n-1 = 0.75*h(n-1) + 0.25*h(n)   (row -1 doesn't exist)
        if (n > 0)
            store_row_v8(oi + (2 * n - 1) * W_OUT + oc, hp, h, 0.75f, 0.25f);
        // out row 2n   = 0.25*h(n-1) + 0.75*h(n)
        store_row_v8(oi + (2 * n) * W_OUT + oc, hp, h, 0.25f, 0.75f);

        #pragma unroll
        for (int j = 0; j < 8; ++j) hp[j] = h[j];
    }

    // last output row 2H-1 = 0.75*h(H-1), owned by the last strip
    if (r0 + RPW == H_IN) {
        float z[8] = {0, 0, 0, 0, 0, 0, 0, 0};
        store_row_v8(oi + (H_OUT - 1) * W_OUT + oc, hp, z, 0.75f, 0.0f);
    }
}

extern "C" void kernel_launch(void* const* d_in, const int* in_sizes, int n_in,
                              void* d_out, int out_size) {
    const float* x = (const float*)d_in[0];   // [8,128,128,128] fp32
    // d_in[1] is the fixed 4x4 binomial kernel; weights folded into code.
    float* out = (float*)d_out;               // [8,128,256,256] fp32

    const int n_img = in_sizes[0] / (H_IN * W_IN);   // B*C = 1024
    Upsample_63797444215162_kernel<<<n_img * 2, WARPS * 32>>>(x, out);
}